// round 15
// baseline (speedup 1.0000x reference)
#include <cuda_runtime.h>
#include <cuda_bf16.h>
#include <cstdint>

#define NN 8192
#define DD 256
#define HH 64
#define DEG 32

// Scratch: Q, V fp32; K bf16 (written directly by K-GEMM epilogue)
__device__ float g_Q[NN * HH];
__device__ float g_V[NN * HH];
__device__ __nv_bfloat16 g_Kb[NN * HH];

// ===========================================================================
// PTX helpers
// ===========================================================================
__device__ __forceinline__ uint32_t smem_u32(const void* p) {
    uint32_t a;
    asm("{ .reg .u64 t; cvta.to.shared.u64 t, %1; cvt.u32.u64 %0, t; }"
        : "=r"(a) : "l"(p));
    return a;
}
#define LDSM_X4(r, a) \
    asm volatile("ldmatrix.sync.aligned.m8n8.x4.shared.b16 {%0,%1,%2,%3}, [%4];" \
                 : "=r"((r)[0]), "=r"((r)[1]), "=r"((r)[2]), "=r"((r)[3]) : "r"(a))
#define LDSM_X4_T(r, a) \
    asm volatile("ldmatrix.sync.aligned.m8n8.x4.trans.shared.b16 {%0,%1,%2,%3}, [%4];" \
                 : "=r"((r)[0]), "=r"((r)[1]), "=r"((r)[2]), "=r"((r)[3]) : "r"(a))
#define MMA_BF16(c, a, b0, b1) \
    asm volatile("mma.sync.aligned.m16n8k16.row.col.f32.bf16.bf16.f32 " \
                 "{%0,%1,%2,%3}, {%4,%5,%6,%7}, {%8,%9}, {%0,%1,%2,%3};" \
                 : "+f"((c)[0]), "+f"((c)[1]), "+f"((c)[2]), "+f"((c)[3]) \
                 : "r"((a)[0]), "r"((a)[1]), "r"((a)[2]), "r"((a)[3]), \
                   "r"(b0), "r"(b1))
#define STS64(addr, v0, v1) \
    asm volatile("st.shared.v2.b32 [%0], {%1,%2};" :: "r"(addr), "r"(v0), "r"(v1) : "memory")

__device__ __forceinline__ uint32_t pack2(__nv_bfloat16 lo, __nv_bfloat16 hi) {
    return ((uint32_t)__bfloat16_as_ushort(hi) << 16) | __bfloat16_as_ushort(lo);
}
// bf16 pair word -> two floats (bf16 is the high half of fp32)
__device__ __forceinline__ float bflo(uint32_t w) { return __uint_as_float(w << 16); }
__device__ __forceinline__ float bfhi(uint32_t w) { return __uint_as_float(w & 0xffff0000u); }

// ---------------------------------------------------------------------------
// Kernel 1: ALL THREE projections in one launch, conversion fused into staging.
// grid = 192 CTAs:
//   blocks [0,64)    : V tile  (precise 3-term bf16 split, fp32 out, no bias)
//   blocks [64,128)  : Q tile  (single bf16, +bias, fp32 out)
//   blocks [128,192) : K tile  (single bf16, +bias, bf16 out)
// A tile staged by direct fp32 LDG + in-register bf16 convert (+ lo residual
// for V). x is read 3x but is fully L2-resident (8 MB << 126 MB L2).
// ---------------------------------------------------------------------------
#define A_BYTES 67584u   // 128*264*2
#define B_BYTES 36864u   // 256*72*2
#define SM_QK (A_BYTES + B_BYTES)
#define SM_V  (2u * (A_BYTES + B_BYTES))

__global__ __launch_bounds__(256) void qkv_mma(
    const float* __restrict__ x,
    const float* __restrict__ Wq, const float* __restrict__ bq,
    const float* __restrict__ Wk, const float* __restrict__ bk,
    const float* __restrict__ Wv)
{
    extern __shared__ char dyn_sm[];
    const int b = blockIdx.x;
    const bool precise = (b < 64);
    const int which = precise ? 2 : (b < 128 ? 0 : 1);   // 0=Q,1=K,2=V
    const float* __restrict__ W    = precise ? Wv : (which ? Wk : Wq);
    const float* __restrict__ bias = precise ? nullptr : (which ? bk : bq);
    const int rowBase = (b & 63) * 128;

    const int tid  = threadIdx.x;
    const int lane = tid & 31;
    const int wid  = tid >> 5;
    const int wm   = wid >> 1;
    const int wn   = wid & 1;

    const uint32_t sb  = smem_u32(dyn_sm);
    const uint32_t aHi = sb;
    const uint32_t bHi = sb + A_BYTES;

    // ---- stage A: direct fp32 loads of x tile, convert to bf16 (hi [+lo]) ----
    // 128 rows x 256 cols fp32 = 8192 float4 chunks; 32 per thread.
#pragma unroll
    for (int i = 0; i < 32; i++) {
        int c  = tid + i * 256;          // 0..8191
        int m  = c >> 6;                 // 0..127
        int k4 = c & 63;                 // float4 index within row
        float4 v = *(const float4*)&x[(size_t)(rowBase + m) * DD + k4 * 4];
        uint32_t so = (uint32_t)m * 528u + (uint32_t)k4 * 8u;
        __nv_bfloat16 h0 = __float2bfloat16(v.x), h1 = __float2bfloat16(v.y);
        __nv_bfloat16 h2 = __float2bfloat16(v.z), h3 = __float2bfloat16(v.w);
        STS64(aHi + so, pack2(h0, h1), pack2(h2, h3));
        if (precise) {
            __nv_bfloat16 l0 = __float2bfloat16(v.x - __bfloat162float(h0));
            __nv_bfloat16 l1 = __float2bfloat16(v.y - __bfloat162float(h1));
            __nv_bfloat16 l2 = __float2bfloat16(v.z - __bfloat162float(h2));
            __nv_bfloat16 l3 = __float2bfloat16(v.w - __bfloat162float(h3));
            STS64(aHi + SM_QK + so, pack2(l0, l1), pack2(l2, l3));
        }
    }

    // ---- stage B = W[k][n] with inline convert ----
#pragma unroll
    for (int i = 0; i < 16; i++) {
        int e4 = tid + i * 256;
        int k  = e4 >> 4;
        int n  = (e4 & 15) * 4;
        float4 w = *(const float4*)&W[(size_t)k * HH + n];
        uint32_t so = (uint32_t)k * 144u + (uint32_t)n * 2u;
        __nv_bfloat16 h0 = __float2bfloat16(w.x), h1 = __float2bfloat16(w.y);
        __nv_bfloat16 h2 = __float2bfloat16(w.z), h3 = __float2bfloat16(w.w);
        STS64(bHi + so, pack2(h0, h1), pack2(h2, h3));
        if (precise) {
            __nv_bfloat16 l0 = __float2bfloat16(w.x - __bfloat162float(h0));
            __nv_bfloat16 l1 = __float2bfloat16(w.y - __bfloat162float(h1));
            __nv_bfloat16 l2 = __float2bfloat16(w.z - __bfloat162float(h2));
            __nv_bfloat16 l3 = __float2bfloat16(w.w - __bfloat162float(h3));
            STS64(bHi + SM_QK + so, pack2(l0, l1), pack2(l2, l3));
        }
    }
    __syncthreads();

    const uint32_t laneRow = lane & 15;
    const uint32_t laneSel = (uint32_t)(lane >> 4) * 16u;
    const uint32_t aAddr = aHi + ((uint32_t)wm * 32u + laneRow) * 528u + laneSel;
    const uint32_t bAddr = bHi + laneRow * 144u + laneSel + (uint32_t)wn * 64u;

    float acc[2][4][4];
#pragma unroll
    for (int mi = 0; mi < 2; mi++)
#pragma unroll
        for (int ni = 0; ni < 4; ni++)
#pragma unroll
            for (int q = 0; q < 4; q++) acc[mi][ni][q] = 0.f;

#pragma unroll
    for (int ks = 0; ks < 16; ks++) {
        uint32_t ak = aAddr + (uint32_t)ks * 32u;
        uint32_t bk2 = bAddr + (uint32_t)ks * 2304u;
        uint32_t ah[2][4], bh[2][4];
        LDSM_X4(ah[0], ak);
        LDSM_X4(ah[1], ak + 16u * 528u);
        LDSM_X4_T(bh[0], bk2);
        LDSM_X4_T(bh[1], bk2 + 32u);
#pragma unroll
        for (int mi = 0; mi < 2; mi++)
#pragma unroll
            for (int ni = 0; ni < 4; ni++)
                MMA_BF16(acc[mi][ni], ah[mi], bh[ni >> 1][(ni & 1) * 2],
                         bh[ni >> 1][(ni & 1) * 2 + 1]);
        if (precise) {
            uint32_t al[2][4], bl[2][4];
            LDSM_X4(al[0], ak + SM_QK);
            LDSM_X4(al[1], ak + SM_QK + 16u * 528u);
            LDSM_X4_T(bl[0], bk2 + SM_QK);
            LDSM_X4_T(bl[1], bk2 + SM_QK + 32u);
#pragma unroll
            for (int mi = 0; mi < 2; mi++)
#pragma unroll
                for (int ni = 0; ni < 4; ni++) {
                    MMA_BF16(acc[mi][ni], ah[mi], bl[ni >> 1][(ni & 1) * 2],
                             bl[ni >> 1][(ni & 1) * 2 + 1]);
                    MMA_BF16(acc[mi][ni], al[mi], bh[ni >> 1][(ni & 1) * 2],
                             bh[ni >> 1][(ni & 1) * 2 + 1]);
                }
        }
    }

    // ---- epilogue ----
    const int groupRow = lane >> 2;
    const int colBase  = (lane & 3) * 2;
#pragma unroll
    for (int mi = 0; mi < 2; mi++) {
        int r = rowBase + wm * 32 + mi * 16 + groupRow;
#pragma unroll
        for (int ni = 0; ni < 4; ni++) {
            int col = wn * 32 + ni * 8 + colBase;
            float bx = 0.f, by = 0.f;
            if (bias) { bx = bias[col]; by = bias[col + 1]; }
            float v00 = acc[mi][ni][0] + bx, v01 = acc[mi][ni][1] + by;
            float v10 = acc[mi][ni][2] + bx, v11 = acc[mi][ni][3] + by;
            if (which == 2) {
                *(float2*)&g_V[(size_t)r * HH + col]       = make_float2(v00, v01);
                *(float2*)&g_V[(size_t)(r + 8) * HH + col] = make_float2(v10, v11);
            } else if (which == 0) {
                *(float2*)&g_Q[(size_t)r * HH + col]       = make_float2(v00, v01);
                *(float2*)&g_Q[(size_t)(r + 8) * HH + col] = make_float2(v10, v11);
            } else {
                *(uint32_t*)&g_Kb[(size_t)r * HH + col] =
                    pack2(__float2bfloat16(v00), __float2bfloat16(v01));
                *(uint32_t*)&g_Kb[(size_t)(r + 8) * HH + col] =
                    pack2(__float2bfloat16(v10), __float2bfloat16(v11));
            }
        }
    }
}

// ---------------------------------------------------------------------------
// Kernel 2: sparse attention, TWO nodes per warp. grid = NN/16 x 256.
// Lane l owns permuted edge e(l) = 4*(l&7) + (l>>3); inverse lane(e)=8*(e&3)+(e>>2).
// ---------------------------------------------------------------------------
__global__ __launch_bounds__(256) void attn_kernel(
    const int* __restrict__ dst,
    const int* __restrict__ edge_type,
    const float* __restrict__ edge_k_emb,
    float* __restrict__ out)
{
    const unsigned FULL = 0xffffffffu;
    const int lane = threadIdx.x & 31;
    const int warp = threadIdx.x >> 5;
    const int n0 = (blockIdx.x * 8 + warp) * 2;   // nodes n0, n0+1

    const int h = lane >> 3;        // 0..3
    const int c = lane & 7;         // 0..7
    const int myedge = 4 * c + h;

    int   jj[2];
    float ekk[2];
    float4 qa[2], qb[2];
#pragma unroll
    for (int u = 0; u < 2; u++) {
        const int node = n0 + u;
        jj[u]  = dst[node * DEG + myedge];
        ekk[u] = edge_k_emb[edge_type[node * DEG + myedge]];
        const float4* qp = (const float4*)&g_Q[(size_t)node * HH + 8 * c];
        qa[u] = qp[0];
        qb[u] = qp[1];
    }

    // ---- K phase: partial dots, both nodes interleaved ----
    float s[2][8];
#pragma unroll
    for (int t = 0; t < 8; t++) {
#pragma unroll
        for (int u = 0; u < 2; u++) {
            int jrow = __shfl_sync(FULL, jj[u], 8 * h + t);   // lane(4t+h)
            uint4 kw = *(const uint4*)&g_Kb[(size_t)jrow * HH + 8 * c];
            float r = qa[u].x * bflo(kw.x);
            r = fmaf(qa[u].y, bfhi(kw.x), r);
            r = fmaf(qa[u].z, bflo(kw.y), r);
            r = fmaf(qa[u].w, bfhi(kw.y), r);
            r = fmaf(qb[u].x, bflo(kw.z), r);
            r = fmaf(qb[u].y, bfhi(kw.z), r);
            r = fmaf(qb[u].z, bflo(kw.w), r);
            r = fmaf(qb[u].w, bfhi(kw.w), r);
            s[u][t] = r;
        }
    }

    // ---- transpose-reduce 8 regs across 8-lane col-groups, per node ----
#pragma unroll
    for (int off = 4; off >= 1; off >>= 1) {
        const bool hiC = (c & off) != 0;
#pragma unroll
        for (int r = 0; r < 4; r++) {
            if (r < off) {
#pragma unroll
                for (int u = 0; u < 2; u++) {
                    float keep = hiC ? s[u][r + off] : s[u][r];
                    float send = hiC ? s[u][r] : s[u][r + off];
                    s[u][r] = keep + __shfl_xor_sync(FULL, send, off);
                }
            }
        }
    }

    // ---- warp softmax over 32 edges, both nodes interleaved ----
    float score[2], p[2];
#pragma unroll
    for (int u = 0; u < 2; u++) score[u] = (s[u][0] + ekk[u]) * (1.0f / 512.0f);

    float m0 = score[0], m1 = score[1];
#pragma unroll
    for (int off = 16; off >= 1; off >>= 1) {
        m0 = fmaxf(m0, __shfl_xor_sync(FULL, m0, off));
        m1 = fmaxf(m1, __shfl_xor_sync(FULL, m1, off));
    }
    float e0 = __expf(score[0] - m0);
    float e1 = __expf(score[1] - m1);
    float s0 = e0, s1 = e1;
#pragma unroll
    for (int off = 16; off >= 1; off >>= 1) {
        s0 += __shfl_xor_sync(FULL, s0, off);
        s1 += __shfl_xor_sync(FULL, s1, off);
    }
    p[0] = e0 / s0;
    p[1] = e1 / s1;

    // ---- V phase: lane covers cols 4cg..4cg+3, edges 2t+half, per node ----
    const int half = lane >> 4;
    const int cg   = lane & 15;
    float4 f0 = make_float4(0.f, 0.f, 0.f, 0.f);
    float4 f1 = make_float4(0.f, 0.f, 0.f, 0.f);
#pragma unroll
    for (int t = 0; t < 16; t++) {
        int e   = 2 * t + half;
        int src = 8 * (e & 3) + (e >> 2);          // lane(e)
        float pk0 = __shfl_sync(FULL, p[0], src);
        int   jk0 = __shfl_sync(FULL, jj[0], src);
        float pk1 = __shfl_sync(FULL, p[1], src);
        int   jk1 = __shfl_sync(FULL, jj[1], src);
        float4 v0 = *(const float4*)&g_V[(size_t)jk0 * HH + 4 * cg];
        float4 v1 = *(const float4*)&g_V[(size_t)jk1 * HH + 4 * cg];
        f0.x = fmaf(pk0, v0.x, f0.x);
        f0.y = fmaf(pk0, v0.y, f0.y);
        f0.z = fmaf(pk0, v0.z, f0.z);
        f0.w = fmaf(pk0, v0.w, f0.w);
        f1.x = fmaf(pk1, v1.x, f1.x);
        f1.y = fmaf(pk1, v1.y, f1.y);
        f1.z = fmaf(pk1, v1.z, f1.z);
        f1.w = fmaf(pk1, v1.w, f1.w);
    }
    // combine the two edge-halves (lane ^ 16 has the same cg)
    f0.x += __shfl_xor_sync(FULL, f0.x, 16);
    f0.y += __shfl_xor_sync(FULL, f0.y, 16);
    f0.z += __shfl_xor_sync(FULL, f0.z, 16);
    f0.w += __shfl_xor_sync(FULL, f0.w, 16);
    f1.x += __shfl_xor_sync(FULL, f1.x, 16);
    f1.y += __shfl_xor_sync(FULL, f1.y, 16);
    f1.z += __shfl_xor_sync(FULL, f1.z, 16);
    f1.w += __shfl_xor_sync(FULL, f1.w, 16);

    if (lane < 16) {
        *(float4*)&out[(size_t)n0 * HH + 4 * lane]       = f0;
        *(float4*)&out[(size_t)(n0 + 1) * HH + 4 * lane] = f1;
    }
}

// ---------------------------------------------------------------------------
// Launch
// ---------------------------------------------------------------------------
extern "C" void kernel_launch(void* const* d_in, const int* in_sizes, int n_in,
                              void* d_out, int out_size)
{
    const float* x          = (const float*)d_in[0];
    const int*   dst        = (const int*)d_in[2];
    const int*   edge_type  = (const int*)d_in[3];
    const float* W_q        = (const float*)d_in[4];
    const float* b_q        = (const float*)d_in[5];
    const float* W_k        = (const float*)d_in[6];
    const float* b_k        = (const float*)d_in[7];
    const float* W_v        = (const float*)d_in[8];
    const float* edge_k_emb = (const float*)d_in[9];
    float* out = (float*)d_out;

    cudaFuncSetAttribute(qkv_mma,
                         cudaFuncAttributeMaxDynamicSharedMemorySize, SM_V);

    qkv_mma<<<192, 256, SM_V>>>(x, W_q, b_q, W_k, b_k, W_v);
    attn_kernel<<<NN / 16, 256>>>(dst, edge_type, edge_k_emb, out);
}